// round 8
// baseline (speedup 1.0000x reference)
#include <cuda_runtime.h>
#include <math.h>
#include <float.h>

#define N_NODES 50000
#define MAX_E   800000
#define IN_C    96
#define HID_C   64
#define OUT_C   40

// ---------------- scratch (no allocations allowed) ----------------
__device__ int   g_is64;
__device__ int   g_src[MAX_E];
__device__ int   g_dst[MAX_E];
__device__ int   g_cnt[N_NODES];
__device__ int   g_rowptr[N_NODES + 1];
__device__ int   g_fill[N_NODES];
__device__ int   g_col[MAX_E];
__device__ float g_wgt[MAX_E];
__device__ float g_dinv[N_NODES];
__device__ float g_dinv2[N_NODES];
__device__ int   g_bsum[64];
__device__ float g_fb[3][N_NODES * HID_C];   // 64-ch ping-pong buffers
__device__ float g_f40[2][N_NODES * OUT_C];  // 40-ch buffers

// ---------------- setup kernels ----------------
__global__ void k_detect(const long long* p, int E) {
    // int64 data: every value in [0, 50000). int32 data viewed as int64:
    // value = lo + hi*2^32 with hi almost surely nonzero -> out of range.
    int ok = 1;
    int step = E / 16;
    for (int i = 0; i < 16; i++) {
        long long v = p[(size_t)i * step];
        if (v < 0 || v >= N_NODES) ok = 0;
    }
    g_is64 = ok;
}

__global__ void k_zero_cnt() {
    int i = blockIdx.x * blockDim.x + threadIdx.x;
    if (i < N_NODES) g_cnt[i] = 0;
}

__global__ void k_decode_count(const void* ei, int E) {
    int e = blockIdx.x * blockDim.x + threadIdx.x;
    if (e >= E) return;
    int s, d;
    if (g_is64) {
        const long long* p = (const long long*)ei;
        s = (int)p[e];
        d = (int)p[(size_t)E + e];
    } else {
        const int* p = (const int*)ei;
        s = p[e];
        d = p[E + e];
    }
    g_src[e] = s;
    g_dst[e] = d;
    atomicAdd(&g_cnt[d], 1);
}

__global__ void k_dinv() {
    int i = blockIdx.x * blockDim.x + threadIdx.x;
    if (i >= N_NODES) return;
    float deg = (float)(g_cnt[i] + 1);   // +1 self loop
    g_dinv[i]  = rsqrtf(deg);
    g_dinv2[i] = 1.0f / deg;             // self-loop norm = dinv^2
}

// ---------------- exclusive scan over g_cnt -> g_rowptr (3 passes) --------
#define SCAN_CHUNK 1024
#define SCAN_NBLK  ((N_NODES + SCAN_CHUNK - 1) / SCAN_CHUNK)   // 49

__global__ void k_scan1() {
    __shared__ int sh[SCAN_CHUNK];
    int t = threadIdx.x;
    int idx = blockIdx.x * SCAN_CHUNK + t;
    sh[t] = (idx < N_NODES) ? g_cnt[idx] : 0;
    __syncthreads();
    for (int off = SCAN_CHUNK >> 1; off > 0; off >>= 1) {
        if (t < off) sh[t] += sh[t + off];
        __syncthreads();
    }
    if (t == 0) g_bsum[blockIdx.x] = sh[0];
}

__global__ void k_scan2(int E) {
    int run = 0;
    for (int i = 0; i < SCAN_NBLK; i++) {
        int v = g_bsum[i];
        g_bsum[i] = run;
        run += v;
    }
    g_rowptr[N_NODES] = run;   // == E
    (void)E;
}

__global__ void k_scan3() {
    __shared__ int sh[SCAN_CHUNK];
    int t = threadIdx.x;
    int idx = blockIdx.x * SCAN_CHUNK + t;
    int v = (idx < N_NODES) ? g_cnt[idx] : 0;
    sh[t] = v;
    __syncthreads();
    for (int off = 1; off < SCAN_CHUNK; off <<= 1) {
        int x = (t >= off) ? sh[t - off] : 0;
        __syncthreads();
        sh[t] += x;
        __syncthreads();
    }
    if (idx < N_NODES) {
        int ex = sh[t] - v + g_bsum[blockIdx.x];
        g_rowptr[idx] = ex;
        g_fill[idx]   = ex;
    }
}

__global__ void k_fill(int E) {
    int e = blockIdx.x * blockDim.x + threadIdx.x;
    if (e >= E) return;
    int s = g_src[e], d = g_dst[e];
    int pos = atomicAdd(&g_fill[d], 1);
    g_col[pos] = s;
    g_wgt[pos] = g_dinv[s] * g_dinv[d];
}

// ---------------- GEMM 1: H0 = X @ W0^T  (N x 96 -> N x 64) ----------------
__global__ void k_gemm0(const float* __restrict__ x, const float* __restrict__ W0) {
    __shared__ float sWt[IN_C * HID_C];   // [k][c] = W0[c*96+k], 24 KB
    __shared__ float sx[4 * IN_C];
    int tid = threadIdx.x;
    int node0 = blockIdx.x * 4;
    for (int i = tid; i < IN_C * HID_C; i += 256) {
        int k = i >> 6, c = i & 63;
        sWt[i] = W0[c * IN_C + k];
    }
    for (int i = tid; i < 4 * IN_C; i += 256) {
        int r = i / IN_C, k = i % IN_C;
        int node = node0 + r;
        sx[i] = (node < N_NODES) ? x[node * IN_C + k] : 0.0f;
    }
    __syncthreads();
    int r = tid >> 6, c = tid & 63;
    int node = node0 + r;
    if (node >= N_NODES) return;
    float acc = 0.0f;
#pragma unroll
    for (int k = 0; k < IN_C; k++)
        acc += sx[r * IN_C + k] * sWt[k * HID_C + c];
    g_fb[0][node * HID_C + c] = acc;
}

// ---------------- GEMM 2: Y = H @ W4^T  (N x 64 -> N x 40) ----------------
__global__ void k_gemm4(const float* __restrict__ W4, int in_i) {
    __shared__ float sWt[HID_C * OUT_C];   // [k][c] = W4[c*64+k], 10 KB
    __shared__ float sh[8 * HID_C];
    const float* __restrict__ hin = g_fb[in_i];
    int tid = threadIdx.x;                 // 320 threads
    int node0 = blockIdx.x * 8;
    for (int i = tid; i < HID_C * OUT_C; i += 320) {
        int k = i / OUT_C, c = i % OUT_C;
        sWt[i] = W4[c * HID_C + k];
    }
    for (int i = tid; i < 8 * HID_C; i += 320) {
        int r = i >> 6, k = i & 63;
        int node = node0 + r;
        sh[i] = (node < N_NODES) ? hin[node * HID_C + k] : 0.0f;
    }
    __syncthreads();
    int r = tid / OUT_C, c = tid % OUT_C;
    int node = node0 + r;
    if (node >= N_NODES) return;
    float acc = 0.0f;
#pragma unroll
    for (int k = 0; k < HID_C; k++)
        acc += sh[r * HID_C + k] * sWt[k * OUT_C + c];
    g_f40[0][node * OUT_C + c] = acc;
}

// ---------------- prop, 64 channels, one warp per node ----------------
// mode 0: out = S h
// mode 1: out = S h + bias
// mode 2: out = 0.8 * S h + 0.2 * h0
// mode 3: out = leaky_relu(0.8 * S h + 0.2 * h0)
__global__ void k_prop64(int in_i, int h0_i, const float* __restrict__ bias,
                         int out_i, int mode) {
    int gw = (blockIdx.x * blockDim.x + threadIdx.x) >> 5;
    int lane = threadIdx.x & 31;
    if (gw >= N_NODES) return;
    const float2* __restrict__ h2 = (const float2*)g_fb[in_i];
    int r0 = g_rowptr[gw], r1 = g_rowptr[gw + 1];
    float dl = g_dinv2[gw];
    float2 hv = h2[gw * 32 + lane];
    float ax = dl * hv.x, ay = dl * hv.y;
    for (int base = r0; base < r1; base += 32) {
        int e = base + lane;
        int cc = 0; float wv = 0.0f;
        if (e < r1) { cc = g_col[e]; wv = g_wgt[e]; }
        int m = min(32, r1 - base);
#pragma unroll 4
        for (int j = 0; j < m; j++) {
            int   s  = __shfl_sync(0xffffffffu, cc, j);
            float ww = __shfl_sync(0xffffffffu, wv, j);
            float2 v = h2[s * 32 + lane];
            ax += ww * v.x;
            ay += ww * v.y;
        }
    }
    int o = gw * 32 + lane;
    float2 r;
    if (mode == 0) {
        r.x = ax; r.y = ay;
    } else if (mode == 1) {
        r.x = ax + bias[2 * lane];
        r.y = ay + bias[2 * lane + 1];
    } else {
        const float2* __restrict__ h02 = (const float2*)g_fb[h0_i];
        float2 z = h02[o];
        r.x = 0.8f * ax + 0.2f * z.x;
        r.y = 0.8f * ay + 0.2f * z.y;
        if (mode == 3) {
            r.x = (r.x > 0.0f) ? r.x : 0.01f * r.x;
            r.y = (r.y > 0.0f) ? r.y : 0.01f * r.y;
        }
    }
    ((float2*)g_fb[out_i])[o] = r;
}

// ---------------- prop, 40 channels ----------------
// mode 0: g_f40[0] -> g_f40[1], plain
// mode 1: g_f40[1] -> dout, + b4, then row-wise log_softmax (fused)
__global__ void k_prop40(const float* __restrict__ b4, float* __restrict__ dout,
                         int mode) {
    int gw = (blockIdx.x * blockDim.x + threadIdx.x) >> 5;
    int lane = threadIdx.x & 31;
    if (gw >= N_NODES) return;
    const float* __restrict__ h = mode ? g_f40[1] : g_f40[0];
    int r0 = g_rowptr[gw], r1 = g_rowptr[gw + 1];
    bool hi = (lane < 8);
    float dl = g_dinv2[gw];
    float a0 = dl * h[gw * OUT_C + lane];
    float a1 = hi ? dl * h[gw * OUT_C + 32 + lane] : 0.0f;
    for (int base = r0; base < r1; base += 32) {
        int e = base + lane;
        int cc = 0; float wv = 0.0f;
        if (e < r1) { cc = g_col[e]; wv = g_wgt[e]; }
        int m = min(32, r1 - base);
#pragma unroll 4
        for (int j = 0; j < m; j++) {
            int   s  = __shfl_sync(0xffffffffu, cc, j);
            float ww = __shfl_sync(0xffffffffu, wv, j);
            a0 += ww * h[s * OUT_C + lane];
            if (hi) a1 += ww * h[s * OUT_C + 32 + lane];
        }
    }
    if (mode == 0) {
        float* o = g_f40[1];
        o[gw * OUT_C + lane] = a0;
        if (hi) o[gw * OUT_C + 32 + lane] = a1;
    } else {
        float v0 = a0 + b4[lane];
        float v1 = hi ? (a1 + b4[32 + lane]) : -FLT_MAX;
        float mx = fmaxf(v0, v1);
#pragma unroll
        for (int off = 16; off > 0; off >>= 1)
            mx = fmaxf(mx, __shfl_xor_sync(0xffffffffu, mx, off));
        float se = expf(v0 - mx) + (hi ? expf(v1 - mx) : 0.0f);
#pragma unroll
        for (int off = 16; off > 0; off >>= 1)
            se += __shfl_xor_sync(0xffffffffu, se, off);
        float l = mx + logf(se);
        dout[gw * OUT_C + lane] = v0 - l;
        if (hi) dout[gw * OUT_C + 32 + lane] = v1 - l;
    }
}

// ---------------- launch ----------------
extern "C" void kernel_launch(void* const* d_in, const int* in_sizes, int n_in,
                              void* d_out, int out_size) {
    const float* x  = (const float*)d_in[0];
    const void*  ei = d_in[1];
    const float* W0 = (const float*)d_in[2];
    const float* b0 = (const float*)d_in[3];
    const float* W4 = (const float*)d_in[4];
    const float* b4 = (const float*)d_in[5];
    float* out = (float*)d_out;
    int E = in_sizes[1] / 2;

    int nb_n = (N_NODES + 255) / 256;
    int nb_e = (E + 255) / 256;
    int nb_w = (N_NODES * 32 + 255) / 256;   // one warp per node, 256 thr/block

    // --- CSR build (deterministic up to fp-sum order, within tolerance) ---
    k_detect<<<1, 1>>>((const long long*)ei, E);
    k_zero_cnt<<<nb_n, 256>>>();
    k_decode_count<<<nb_e, 256>>>(ei, E);
    k_dinv<<<nb_n, 256>>>();
    k_scan1<<<SCAN_NBLK, SCAN_CHUNK>>>();
    k_scan2<<<1, 1>>>(E);
    k_scan3<<<SCAN_NBLK, SCAN_CHUNK>>>();
    k_fill<<<nb_e, 256>>>(E);

    // --- conv0 (SGConv): h = S^2(x W0^T) + b0 ---
    k_gemm0<<<(N_NODES + 3) / 4, 256>>>(x, W0);           // fb0 = x W0^T
    k_prop64<<<nb_w, 256>>>(0, 0, b0, 1, 0);              // fb1 = S fb0
    k_prop64<<<nb_w, 256>>>(1, 0, b0, 0, 1);              // fb0 = S fb1 + b0

    // --- conv1 APPNP + lrelu (h0 = fb0) ---
    k_prop64<<<nb_w, 256>>>(0, 0, b0, 1, 2);              // fb1 = .8 S fb0 + .2 fb0
    k_prop64<<<nb_w, 256>>>(1, 0, b0, 2, 3);              // fb2 = lrelu(.8 S fb1 + .2 fb0)
    // --- conv2 (h0 = fb2) ---
    k_prop64<<<nb_w, 256>>>(2, 2, b0, 0, 2);              // fb0
    k_prop64<<<nb_w, 256>>>(0, 2, b0, 1, 3);              // fb1
    // --- conv3 (h0 = fb1) ---
    k_prop64<<<nb_w, 256>>>(1, 1, b0, 0, 2);              // fb0
    k_prop64<<<nb_w, 256>>>(0, 1, b0, 2, 3);              // fb2

    // --- conv4 (SGConv): out = log_softmax(S^2(h W4^T) + b4) ---
    k_gemm4<<<(N_NODES + 7) / 8, 320>>>(W4, 2);           // f40[0] = fb2 W4^T
    k_prop40<<<nb_w, 256>>>(b4, out, 0);                  // f40[1] = S f40[0]
    k_prop40<<<nb_w, 256>>>(b4, out, 1);                  // out = lsm(S f40[1] + b4)
}

// round 9
// speedup vs baseline: 1.0436x; 1.0436x over previous
#include <cuda_runtime.h>
#include <cuda_fp16.h>
#include <math.h>
#include <float.h>

#define N_NODES 50000
#define MAX_E   800000
#define IN_C    96
#define HID_C   64
#define OUT_C   40

// ---------------- scratch (no allocations allowed) ----------------
__device__ int    g_is64;
__device__ int    g_src[MAX_E];
__device__ int    g_dst[MAX_E];
__device__ int    g_cnt[N_NODES];
__device__ int    g_rowptr[N_NODES + 1];
__device__ int    g_fill[N_NODES];
__device__ int    g_col[MAX_E];
__device__ float  g_wgt[MAX_E];
__device__ float  g_dinv[N_NODES];
__device__ float  g_dinv2[N_NODES];
__device__ int    g_bsum[64];
__device__ __half g_hb[3][N_NODES * HID_C];   // 64-ch fp16 ping-pong buffers
__device__ __half g_h40[2][N_NODES * OUT_C];  // 40-ch fp16 buffers

// ---------------- setup: zero counts + dtype detection ----------------
__global__ void k_init(const long long* p, int E) {
    int i = blockIdx.x * blockDim.x + threadIdx.x;
    if (i < N_NODES) g_cnt[i] = 0;
    if (i == 0) {
        // int64 data: sampled values all in [0, 50000). int32 viewed as int64:
        // lo + hi*2^32 with hi almost surely nonzero -> out of range.
        int ok = 1;
        int step = E / 16;
        for (int k = 0; k < 16; k++) {
            long long v = p[(size_t)k * step];
            if (v < 0 || v >= N_NODES) ok = 0;
        }
        g_is64 = ok;
    }
}

__global__ void k_decode_count(const void* ei, int E) {
    int e = blockIdx.x * blockDim.x + threadIdx.x;
    if (e >= E) return;
    int s, d;
    if (g_is64) {
        const long long* p = (const long long*)ei;
        s = (int)p[e];
        d = (int)p[(size_t)E + e];
    } else {
        const int* p = (const int*)ei;
        s = p[e];
        d = p[E + e];
    }
    g_src[e] = s;
    g_dst[e] = d;
    atomicAdd(&g_cnt[d], 1);
}

// ---------------- exclusive scan over g_cnt -> g_rowptr (3 passes) --------
#define SCAN_CHUNK 1024
#define SCAN_NBLK  ((N_NODES + SCAN_CHUNK - 1) / SCAN_CHUNK)   // 49

__global__ void k_scan1() {   // also computes dinv/dinv2 (cnt is final here)
    __shared__ int sh[SCAN_CHUNK];
    int t = threadIdx.x;
    int idx = blockIdx.x * SCAN_CHUNK + t;
    int c = (idx < N_NODES) ? g_cnt[idx] : 0;
    if (idx < N_NODES) {
        float deg = (float)(c + 1);   // +1 self loop
        g_dinv[idx]  = rsqrtf(deg);
        g_dinv2[idx] = 1.0f / deg;    // self-loop norm = dinv^2
    }
    sh[t] = c;
    __syncthreads();
    for (int off = SCAN_CHUNK >> 1; off > 0; off >>= 1) {
        if (t < off) sh[t] += sh[t + off];
        __syncthreads();
    }
    if (t == 0) g_bsum[blockIdx.x] = sh[0];
}

__global__ void k_scan2() {
    int run = 0;
    for (int i = 0; i < SCAN_NBLK; i++) {
        int v = g_bsum[i];
        g_bsum[i] = run;
        run += v;
    }
    g_rowptr[N_NODES] = run;
}

__global__ void k_scan3() {
    __shared__ int sh[SCAN_CHUNK];
    int t = threadIdx.x;
    int idx = blockIdx.x * SCAN_CHUNK + t;
    int v = (idx < N_NODES) ? g_cnt[idx] : 0;
    sh[t] = v;
    __syncthreads();
    for (int off = 1; off < SCAN_CHUNK; off <<= 1) {
        int x = (t >= off) ? sh[t - off] : 0;
        __syncthreads();
        sh[t] += x;
        __syncthreads();
    }
    if (idx < N_NODES) {
        int ex = sh[t] - v + g_bsum[blockIdx.x];
        g_rowptr[idx] = ex;
        g_fill[idx]   = ex;
    }
}

__global__ void k_fill(int E) {
    int e = blockIdx.x * blockDim.x + threadIdx.x;
    if (e >= E) return;
    int s = g_src[e], d = g_dst[e];
    int pos = atomicAdd(&g_fill[d], 1);
    g_col[pos] = s;
    g_wgt[pos] = g_dinv[s] * g_dinv[d];
}

// ---------------- GEMM 1: H0 = X @ W0^T  (N x 96 -> N x 64, fp16 out) -----
__global__ void k_gemm0(const float* __restrict__ x, const float* __restrict__ W0) {
    __shared__ float sWt[IN_C * HID_C];   // [k][c] = W0[c*96+k], 24 KB
    __shared__ float sx[4 * IN_C];
    int tid = threadIdx.x;
    int node0 = blockIdx.x * 4;
    for (int i = tid; i < IN_C * HID_C; i += 256) {
        int k = i >> 6, c = i & 63;
        sWt[i] = W0[c * IN_C + k];
    }
    for (int i = tid; i < 4 * IN_C; i += 256) {
        int r = i / IN_C, k = i % IN_C;
        int node = node0 + r;
        sx[i] = (node < N_NODES) ? x[node * IN_C + k] : 0.0f;
    }
    __syncthreads();
    int r = tid >> 6, c = tid & 63;
    int node = node0 + r;
    if (node >= N_NODES) return;
    float acc = 0.0f;
#pragma unroll
    for (int k = 0; k < IN_C; k++)
        acc += sx[r * IN_C + k] * sWt[k * HID_C + c];
    g_hb[0][node * HID_C + c] = __float2half_rn(acc);
}

// ---------------- GEMM 2: Y = H @ W4^T  (N x 64 fp16 -> N x 40 fp16) ------
__global__ void k_gemm4(const float* __restrict__ W4, int in_i) {
    __shared__ float sWt[HID_C * OUT_C];   // [k][c] = W4[c*64+k], 10 KB
    __shared__ float sh[8 * HID_C];
    const __half* __restrict__ hin = g_hb[in_i];
    int tid = threadIdx.x;                 // 320 threads
    int node0 = blockIdx.x * 8;
    for (int i = tid; i < HID_C * OUT_C; i += 320) {
        int k = i / OUT_C, c = i % OUT_C;
        sWt[i] = W4[c * HID_C + k];
    }
    for (int i = tid; i < 8 * HID_C; i += 320) {
        int r = i >> 6, k = i & 63;
        int node = node0 + r;
        sh[i] = (node < N_NODES) ? __half2float(hin[node * HID_C + k]) : 0.0f;
    }
    __syncthreads();
    int r = tid / OUT_C, c = tid % OUT_C;
    int node = node0 + r;
    if (node >= N_NODES) return;
    float acc = 0.0f;
#pragma unroll
    for (int k = 0; k < HID_C; k++)
        acc += sh[r * HID_C + k] * sWt[k * OUT_C + c];
    g_h40[0][node * OUT_C + c] = __float2half_rn(acc);
}

// ---------------- prop, 64 channels fp16, one warp per node ----------------
// 64 halves = 128 B per node = ONE L2 line per edge gather.
// mode 0: out = S h
// mode 1: out = S h + bias
// mode 2: out = 0.8 * S h + 0.2 * h0
// mode 3: out = leaky_relu(0.8 * S h + 0.2 * h0)
__global__ void k_prop64(int in_i, int h0_i, const float* __restrict__ bias,
                         int out_i, int mode) {
    int gw = (blockIdx.x * blockDim.x + threadIdx.x) >> 5;
    int lane = threadIdx.x & 31;
    if (gw >= N_NODES) return;
    const __half2* __restrict__ h2 = (const __half2*)g_hb[in_i];
    int r0 = g_rowptr[gw], r1 = g_rowptr[gw + 1];
    float dl = g_dinv2[gw];
    float2 hv = __half22float2(h2[gw * 32 + lane]);
    float ax = dl * hv.x, ay = dl * hv.y;

    int nfull = (r1 - r0) >> 5;
    int e = r0 + lane;
    for (int b = 0; b < nfull; b++) {
        int cc = g_col[e];
        float wv = g_wgt[e];
        e += 32;
#pragma unroll
        for (int j = 0; j < 32; j++) {
            int   s  = __shfl_sync(0xffffffffu, cc, j);
            float ww = __shfl_sync(0xffffffffu, wv, j);
            float2 v = __half22float2(h2[s * 32 + lane]);
            ax += ww * v.x;
            ay += ww * v.y;
        }
    }
    int rem = (r1 - r0) & 31;
    if (rem) {
        int cc = 0; float wv = 0.0f;
        if (lane < rem) { cc = g_col[e]; wv = g_wgt[e]; }
        for (int j = 0; j < rem; j++) {
            int   s  = __shfl_sync(0xffffffffu, cc, j);
            float ww = __shfl_sync(0xffffffffu, wv, j);
            float2 v = __half22float2(h2[s * 32 + lane]);
            ax += ww * v.x;
            ay += ww * v.y;
        }
    }

    int o = gw * 32 + lane;
    float2 r;
    if (mode == 0) {
        r.x = ax; r.y = ay;
    } else if (mode == 1) {
        r.x = ax + bias[2 * lane];
        r.y = ay + bias[2 * lane + 1];
    } else {
        const __half2* __restrict__ h02 = (const __half2*)g_hb[h0_i];
        float2 z = __half22float2(h02[o]);
        r.x = 0.8f * ax + 0.2f * z.x;
        r.y = 0.8f * ay + 0.2f * z.y;
        if (mode == 3) {
            r.x = (r.x > 0.0f) ? r.x : 0.01f * r.x;
            r.y = (r.y > 0.0f) ? r.y : 0.01f * r.y;
        }
    }
    ((__half2*)g_hb[out_i])[o] = __float22half2_rn(r);
}

// ---------------- prop, 40 channels fp16 ----------------
// lanes 0..19 each own one half2 (80 B per node).
// mode 0: g_h40[0] -> g_h40[1], plain
// mode 1: g_h40[1] -> dout (fp32), + b4, then row-wise log_softmax (fused)
__global__ void k_prop40(const float* __restrict__ b4, float* __restrict__ dout,
                         int mode) {
    int gw = (blockIdx.x * blockDim.x + threadIdx.x) >> 5;
    int lane = threadIdx.x & 31;
    if (gw >= N_NODES) return;
    const __half2* __restrict__ h2 = (const __half2*)g_h40[mode ? 1 : 0];
    int r0 = g_rowptr[gw], r1 = g_rowptr[gw + 1];
    bool act = (lane < 20);
    float dl = g_dinv2[gw];
    float a0 = 0.0f, a1 = 0.0f;
    if (act) {
        float2 hv = __half22float2(h2[gw * 20 + lane]);
        a0 = dl * hv.x;
        a1 = dl * hv.y;
    }
    for (int base = r0; base < r1; base += 32) {
        int e = base + lane;
        int cc = 0; float wv = 0.0f;
        if (e < r1) { cc = g_col[e]; wv = g_wgt[e]; }
        int m = min(32, r1 - base);
        for (int j = 0; j < m; j++) {
            int   s  = __shfl_sync(0xffffffffu, cc, j);
            float ww = __shfl_sync(0xffffffffu, wv, j);
            if (act) {
                float2 v = __half22float2(h2[s * 20 + lane]);
                a0 += ww * v.x;
                a1 += ww * v.y;
            }
        }
    }
    if (mode == 0) {
        if (act) {
            float2 r; r.x = a0; r.y = a1;
            ((__half2*)g_h40[1])[gw * 20 + lane] = __float22half2_rn(r);
        }
    } else {
        float v0 = act ? (a0 + b4[2 * lane])     : -FLT_MAX;
        float v1 = act ? (a1 + b4[2 * lane + 1]) : -FLT_MAX;
        float mx = fmaxf(v0, v1);
#pragma unroll
        for (int off = 16; off > 0; off >>= 1)
            mx = fmaxf(mx, __shfl_xor_sync(0xffffffffu, mx, off));
        float se = act ? (expf(v0 - mx) + expf(v1 - mx)) : 0.0f;
#pragma unroll
        for (int off = 16; off > 0; off >>= 1)
            se += __shfl_xor_sync(0xffffffffu, se, off);
        float l = mx + logf(se);
        if (act) {
            dout[gw * OUT_C + 2 * lane]     = v0 - l;
            dout[gw * OUT_C + 2 * lane + 1] = v1 - l;
        }
    }
}

// ---------------- launch ----------------
extern "C" void kernel_launch(void* const* d_in, const int* in_sizes, int n_in,
                              void* d_out, int out_size) {
    const float* x  = (const float*)d_in[0];
    const void*  ei = d_in[1];
    const float* W0 = (const float*)d_in[2];
    const float* b0 = (const float*)d_in[3];
    const float* W4 = (const float*)d_in[4];
    const float* b4 = (const float*)d_in[5];
    float* out = (float*)d_out;
    int E = in_sizes[1] / 2;

    int nb_n = (N_NODES + 255) / 256;
    int nb_e = (E + 255) / 256;
    int nb_w = (N_NODES * 32 + 255) / 256;   // one warp per node

    // --- CSR build ---
    k_init<<<nb_n, 256>>>((const long long*)ei, E);
    k_decode_count<<<nb_e, 256>>>(ei, E);
    k_scan1<<<SCAN_NBLK, SCAN_CHUNK>>>();
    k_scan2<<<1, 1>>>();
    k_scan3<<<SCAN_NBLK, SCAN_CHUNK>>>();
    k_fill<<<nb_e, 256>>>(E);

    // --- conv0 (SGConv): h = S^2(x W0^T) + b0 ---
    k_gemm0<<<(N_NODES + 3) / 4, 256>>>(x, W0);           // hb0 = x W0^T
    k_prop64<<<nb_w, 256>>>(0, 0, b0, 1, 0);              // hb1 = S hb0
    k_prop64<<<nb_w, 256>>>(1, 0, b0, 0, 1);              // hb0 = S hb1 + b0

    // --- conv1 APPNP + lrelu (h0 = hb0) ---
    k_prop64<<<nb_w, 256>>>(0, 0, b0, 1, 2);              // hb1
    k_prop64<<<nb_w, 256>>>(1, 0, b0, 2, 3);              // hb2
    // --- conv2 (h0 = hb2) ---
    k_prop64<<<nb_w, 256>>>(2, 2, b0, 0, 2);              // hb0
    k_prop64<<<nb_w, 256>>>(0, 2, b0, 1, 3);              // hb1
    // --- conv3 (h0 = hb1) ---
    k_prop64<<<nb_w, 256>>>(1, 1, b0, 0, 2);              // hb0
    k_prop64<<<nb_w, 256>>>(0, 1, b0, 2, 3);              // hb2

    // --- conv4 (SGConv): out = log_softmax(S^2(h W4^T) + b4) ---
    k_gemm4<<<(N_NODES + 7) / 8, 320>>>(W4, 2);           // h40[0] = hb2 W4^T
    k_prop40<<<nb_w, 256>>>(b4, out, 0);                  // h40[1] = S h40[0]
    k_prop40<<<nb_w, 256>>>(b4, out, 1);                  // out = lsm(S h40[1] + b4)
}